// round 5
// baseline (speedup 1.0000x reference)
#include <cuda_runtime.h>
#include <cuda_bf16.h>
#include <cstdint>

#define TLEN   128
#define THID   64
#define TB     256
#define TN     2048
#define NEGF   (-1.0e9f)
#define NTILE  4            // 64-row tiles per block
#define ROWS_PB (NTILE*64)  // 256 rows per block

// ---------- device scratch (allocation-free rule) ----------
__device__ int           g_pool[TB * TLEN];
__device__ __nv_bfloat16 g_W1bf[128 * 64];
__device__ __nv_bfloat16 g_W2bf[64 * 128];

// ---------- smem layout (bytes) ----------
#define O_X    0                         // [64][136] bf16
#define O_W1   (O_X   + 64*136*2)        // [128][72] bf16
#define O_W2   (O_W1  + 128*72*2)        // [64][136] bf16
#define O_H1   (O_W2  + 64*136*2)        // [64][72]  bf16
#define O_RS   (O_H1  + 64*72*2)         // [64][2] f32
#define O_RQ   (O_RS  + 512)
#define O_MU   (O_RQ  + 512)             // [64] f32
#define O_RSD  (O_MU  + 256)
#define O_POOL (O_RSD + 256)             // [128] int
#define O_B2   (O_POOL+ 512)             // [128] f32
#define O_G    (O_B2  + 512)
#define O_BT   (O_G   + 512)
#define O_B1   (O_BT  + 512)             // [64] f32
#define O_ST   (O_B1  + 256)             // [64][132] f32 staging
#define SMEM_BYTES (O_ST + 64*132*4)

__device__ __forceinline__ uint32_t smem_u32(const void* p) {
    uint32_t a;
    asm("{ .reg .u64 t; cvta.to.shared.u64 t, %1; cvt.u32.u64 %0, t; }" : "=r"(a) : "l"(p));
    return a;
}
__device__ __forceinline__ void ldmA(uint32_t* r, uint32_t addr) {
    asm volatile("ldmatrix.sync.aligned.m8n8.x4.shared.b16 {%0,%1,%2,%3}, [%4];"
        : "=r"(r[0]),"=r"(r[1]),"=r"(r[2]),"=r"(r[3]) : "r"(addr));
}
__device__ __forceinline__ void ldmBT(uint32_t* r, uint32_t addr) {
    asm volatile("ldmatrix.sync.aligned.m8n8.x4.trans.shared.b16 {%0,%1,%2,%3}, [%4];"
        : "=r"(r[0]),"=r"(r[1]),"=r"(r[2]),"=r"(r[3]) : "r"(addr));
}
__device__ __forceinline__ void mma16816(float* c, const uint32_t* a, const uint32_t* b) {
    asm volatile("mma.sync.aligned.m16n8k16.row.col.f32.bf16.bf16.f32 "
        "{%0,%1,%2,%3}, {%4,%5,%6,%7}, {%8,%9}, {%0,%1,%2,%3};"
        : "+f"(c[0]),"+f"(c[1]),"+f"(c[2]),"+f"(c[3])
        : "r"(a[0]),"r"(a[1]),"r"(a[2]),"r"(a[3]), "r"(b[0]),"r"(b[1]));
}

// prep: convert weights to bf16 + init global pool
__global__ void prep_kernel(const float* __restrict__ W1, const float* __restrict__ W2) {
    int i = blockIdx.x * blockDim.x + threadIdx.x;
    if (i < 128 * 64) g_W1bf[i] = __float2bfloat16(W1[i]);
    if (i < 64 * 128) g_W2bf[i] = __float2bfloat16(W2[i]);
    if (i < TB * TLEN) g_pool[i] = __float_as_int(NEGF);
}

__global__ __launch_bounds__(256, 2)
void fused_mlp_kernel(const float* __restrict__ X,
                      const int*   __restrict__ Mk,
                      const float* __restrict__ b1g,
                      const float* __restrict__ b2g,
                      const float* __restrict__ gg,
                      const float* __restrict__ btg,
                      float* __restrict__ out)
{
    extern __shared__ char smc[];
    const uint32_t sb = smem_u32(smc);
    const int tid  = threadIdx.x;
    const int lane = tid & 31, warp = tid >> 5;
    const int base = blockIdx.x * ROWS_PB;
    const int bidx = base >> 11;

    float* fRS  = (float*)(smc + O_RS);
    float* fRQ  = (float*)(smc + O_RQ);
    float* fMu  = (float*)(smc + O_MU);
    float* fRsd = (float*)(smc + O_RSD);
    int*   iPool= (int*)  (smc + O_POOL);
    float* fB1  = (float*)(smc + O_B1);
    float* fB2  = (float*)(smc + O_B2);
    float* fG   = (float*)(smc + O_G);
    float* fBt  = (float*)(smc + O_BT);
    float* fST  = (float*)(smc + O_ST);

    // ---- small params ----
    if (tid < 128) {
        iPool[tid] = __float_as_int(NEGF);
        fB2[tid] = b2g[tid];
        fG[tid]  = gg[tid];
        fBt[tid] = btg[tid];
    } else if (tid - 128 < 64) {
        fB1[tid - 128] = b1g[tid - 128];
    }

    // ---- weights once per block ----
    {
        const uint32_t* gw1 = (const uint32_t*)g_W1bf;
        const uint32_t* gw2 = (const uint32_t*)g_W2bf;
        #pragma unroll
        for (int v = 0; v < 16; v++) {
            int i = tid + 256 * v;
            int k1 = i >> 5, c1 = (i & 31) * 2;
            *(uint32_t*)(smc + O_W1 + k1 * 144 + c1 * 2) = gw1[i];
            int k2 = i >> 6, c2i = (i & 63) * 2;
            *(uint32_t*)(smc + O_W2 + k2 * 272 + c2i * 2) = gw2[i];
        }
    }

    // preload tile 0 into smem (f32 -> bf16)
    {
        const float4* gX = (const float4*)(X + (size_t)base * TLEN);
        #pragma unroll
        for (int v = 0; v < 8; v++) {
            int idx = tid + 256 * v;
            int r = idx >> 5, c = (idx & 31) * 4;
            float4 x = __ldcs(gX + idx);
            __nv_bfloat162* p = (__nv_bfloat162*)(smc + O_X + r * 272 + c * 2);
            p[0] = __floats2bfloat162_rn(x.x, x.y);
            p[1] = __floats2bfloat162_rn(x.z, x.w);
        }
    }
    __syncthreads();

    const int g = lane >> 2, t = lane & 3;
    const int mt = warp & 3;
    const int nh = warp >> 2;
    const int r0 = mt * 16;
    const int am = ((lane >> 3) & 1) * 8 + (lane & 7);
    const int ak = ((lane >> 4) & 1) * 8;
    const int bk = am;
    const int bn = ak;
    const int cb1 = nh * 32;
    const int cb2 = nh * 64;

    float cm[16];
    #pragma unroll
    for (int j = 0; j < 16; j++) cm[j] = NEGF;

    #pragma unroll 1
    for (int tt = 0; tt < NTILE; tt++) {
        const int row0 = base + tt * 64;

        // prefetch next tile's X into registers
        float4 px[8];
        if (tt < NTILE - 1) {
            const float4* gX = (const float4*)(X + (size_t)(row0 + 64) * TLEN);
            #pragma unroll
            for (int v = 0; v < 8; v++) px[v] = __ldcs(gX + tid + 256 * v);
        }
        const int maskL = __ldg(Mk + row0 + r0 + g);
        const int maskH = __ldg(Mk + row0 + r0 + g + 8);

        // ============ GEMM1 ============
        {
            float c1[4][4];
            #pragma unroll
            for (int j = 0; j < 4; j++)
                #pragma unroll
                for (int q = 0; q < 4; q++) c1[j][q] = 0.f;

            uint32_t aB = sb + O_X  + (r0 + am) * 272 + ak * 2;
            uint32_t bB = sb + O_W1 + bk * 144 + (cb1 + bn) * 2;
            #pragma unroll
            for (int ks = 0; ks < 8; ks++) {
                uint32_t a[4], b[8];
                ldmA(a, aB + ks * 32);
                ldmBT(b,     bB + ks * (16 * 144));
                ldmBT(b + 4, bB + ks * (16 * 144) + 32);
                mma16816(c1[0], a, b);
                mma16816(c1[1], a, b + 2);
                mma16816(c1[2], a, b + 4);
                mma16816(c1[3], a, b + 6);
            }
            #pragma unroll
            for (int j = 0; j < 4; j++) {
                int c = cb1 + j * 8 + 2 * t;
                float bb0 = fB1[c], bb1 = fB1[c + 1];
                __nv_bfloat162 lo = __floats2bfloat162_rn(c1[j][0] + bb0, c1[j][1] + bb1);
                __nv_bfloat162 hi = __floats2bfloat162_rn(c1[j][2] + bb0, c1[j][3] + bb1);
                *(__nv_bfloat162*)(smc + O_H1 + (r0 + g) * 144 + c * 2)     = lo;
                *(__nv_bfloat162*)(smc + O_H1 + (r0 + g + 8) * 144 + c * 2) = hi;
            }
        }
        __syncthreads();

        // ============ GEMM2 ============
        float c2[8][4];
        #pragma unroll
        for (int j = 0; j < 8; j++)
            #pragma unroll
            for (int q = 0; q < 4; q++) c2[j][q] = 0.f;
        {
            uint32_t aB = sb + O_H1 + (r0 + am) * 144 + ak * 2;
            uint32_t bB = sb + O_W2 + bk * 272 + (cb2 + bn) * 2;
            #pragma unroll
            for (int ks = 0; ks < 4; ks++) {
                uint32_t a[4];
                ldmA(a, aB + ks * 32);
                #pragma unroll
                for (int jj = 0; jj < 4; jj++) {
                    uint32_t b[4];
                    ldmBT(b, bB + ks * (16 * 272) + jj * 32);
                    mma16816(c2[2 * jj],     a, b);
                    mma16816(c2[2 * jj + 1], a, b + 2);
                }
            }
        }

        // ---- +b2, LN partial sums ----
        {
            float sl = 0.f, ql = 0.f, sh = 0.f, qh = 0.f;
            #pragma unroll
            for (int j = 0; j < 8; j++) {
                int c = cb2 + j * 8 + 2 * t;
                float bb0 = fB2[c], bb1 = fB2[c + 1];
                c2[j][0] += bb0; c2[j][1] += bb1;
                c2[j][2] += bb0; c2[j][3] += bb1;
                sl += c2[j][0] + c2[j][1];
                ql += c2[j][0] * c2[j][0] + c2[j][1] * c2[j][1];
                sh += c2[j][2] + c2[j][3];
                qh += c2[j][2] * c2[j][2] + c2[j][3] * c2[j][3];
            }
            #pragma unroll
            for (int s = 1; s <= 2; s <<= 1) {
                sl += __shfl_xor_sync(0xffffffffu, sl, s);
                ql += __shfl_xor_sync(0xffffffffu, ql, s);
                sh += __shfl_xor_sync(0xffffffffu, sh, s);
                qh += __shfl_xor_sync(0xffffffffu, qh, s);
            }
            if (t == 0) {
                fRS[(r0 + g) * 2 + nh] = sl;     fRQ[(r0 + g) * 2 + nh] = ql;
                fRS[(r0 + g + 8) * 2 + nh] = sh; fRQ[(r0 + g + 8) * 2 + nh] = qh;
            }
        }
        __syncthreads();

        if (tid < 64) {
            float S = fRS[tid * 2] + fRS[tid * 2 + 1];
            float Q = fRQ[tid * 2] + fRQ[tid * 2 + 1];
            float mu  = S * 0.0078125f;
            float var = Q * 0.0078125f - mu * mu;
            fMu[tid]  = mu;
            fRsd[tid] = rsqrtf(var + 1e-3f);
        }
        __syncthreads();

        // ---- normalize + relu + mask -> staging smem; pool max in registers ----
        {
            const float muL = fMu[r0 + g],     rsL = fRsd[r0 + g];
            const float muH = fMu[r0 + g + 8], rsH = fRsd[r0 + g + 8];
            const bool  mkL = (maskL != 0);
            const bool  mkH = (maskH != 0);
            float* stL = fST + (r0 + g) * 132;
            float* stH = fST + (r0 + g + 8) * 132;

            #pragma unroll
            for (int j = 0; j < 8; j++) {
                int c = cb2 + j * 8 + 2 * t;
                float ga0 = fG[c], ga1 = fG[c + 1];
                float be0 = fBt[c], be1 = fBt[c + 1];

                float vL0 = fmaxf((c2[j][0] - muL) * rsL * ga0 + be0, 0.f);
                float vL1 = fmaxf((c2[j][1] - muL) * rsL * ga1 + be1, 0.f);
                float vH0 = fmaxf((c2[j][2] - muH) * rsH * ga0 + be0, 0.f);
                float vH1 = fmaxf((c2[j][3] - muH) * rsH * ga1 + be1, 0.f);
                vL0 = mkL ? vL0 : NEGF;  vL1 = mkL ? vL1 : NEGF;
                vH0 = mkH ? vH0 : NEGF;  vH1 = mkH ? vH1 : NEGF;

                *(float2*)(stL + c) = make_float2(vL0, vL1);
                *(float2*)(stH + c) = make_float2(vH0, vH1);

                cm[2 * j]     = fmaxf(cm[2 * j],     fmaxf(vL0, vH0));
                cm[2 * j + 1] = fmaxf(cm[2 * j + 1], fmaxf(vL1, vH1));
            }
        }

        // store prefetched X tile for next iteration (X buffer free since GEMM1)
        if (tt < NTILE - 1) {
            #pragma unroll
            for (int v = 0; v < 8; v++) {
                int idx = tid + 256 * v;
                int r = idx >> 5, c = (idx & 31) * 4;
                __nv_bfloat162* p = (__nv_bfloat162*)(smc + O_X + r * 272 + c * 2);
                p[0] = __floats2bfloat162_rn(px[v].x, px[v].y);
                p[1] = __floats2bfloat162_rn(px[v].z, px[v].w);
            }
        }
        __syncthreads();

        // ---- coalesced streaming stores: 64 rows x 128 floats ----
        {
            float* ob = out + (size_t)row0 * 256;
            #pragma unroll
            for (int v = 0; v < 8; v++) {
                int idx = tid + 256 * v;          // 0..2047 float4s
                int r = idx >> 5, cq = (idx & 31) * 4;
                float4 val = *(float4*)(fST + r * 132 + cq);
                __stcs((float4*)(ob + (size_t)r * 256 + cq), val);
            }
        }
    }

    // ---- once-per-block pool reduction ----
    #pragma unroll
    for (int j = 0; j < 16; j++) {
        float v = cm[j];
        #pragma unroll
        for (int s = 4; s <= 16; s <<= 1)
            v = fmaxf(v, __shfl_xor_sync(0xffffffffu, v, s));
        cm[j] = v;
    }
    if (g == 0) {
        #pragma unroll
        for (int j = 0; j < 8; j++) {
            int c = cb2 + j * 8 + 2 * t;
            atomicMax(&iPool[c],     __float_as_int(cm[2 * j]));
            atomicMax(&iPool[c + 1], __float_as_int(cm[2 * j + 1]));
        }
    }
    __syncthreads();

    if (tid < 128)
        atomicMax(&g_pool[bidx * 128 + tid], iPool[tid]);
}

// second half of output: broadcast per-batch pooled max
__global__ void bcast_kernel(float* __restrict__ out) {
    int i   = blockIdx.x * blockDim.x + threadIdx.x;
    int d4  = (i & 31) << 2;
    int row = i >> 5;
    int bb  = row >> 11;
    int4 p = *(const int4*)(g_pool + bb * 128 + d4);
    float4 v = make_float4(__int_as_float(p.x), __int_as_float(p.y),
                           __int_as_float(p.z), __int_as_float(p.w));
    __stcs((float4*)(out + (size_t)row * 256 + 128 + d4), v);
}

extern "C" void kernel_launch(void* const* d_in, const int* in_sizes, int n_in,
                              void* d_out, int out_size) {
    const float* X  = (const float*)d_in[0];
    const int*   Mk = (const int*)  d_in[1];
    const float* W1 = (const float*)d_in[2];
    const float* b1 = (const float*)d_in[3];
    const float* W2 = (const float*)d_in[4];
    const float* b2 = (const float*)d_in[5];
    const float* g  = (const float*)d_in[6];
    const float* bt = (const float*)d_in[7];
    float* out = (float*)d_out;

    cudaFuncSetAttribute(fused_mlp_kernel,
                         cudaFuncAttributeMaxDynamicSharedMemorySize, SMEM_BYTES);

    prep_kernel<<<(TB * TLEN + 255) / 256, 256>>>(W1, W2);
    fused_mlp_kernel<<<(TB * TN) / ROWS_PB, 256, SMEM_BYTES>>>(
        X, Mk, b1, b2, g, bt, out);
    bcast_kernel<<<(TB * TN * 32) / 256, 256>>>(out);
}